// round 1
// baseline (speedup 1.0000x reference)
#include <cuda_runtime.h>
#include <math.h>

#define NN   100000
#define FIN  512
#define HC   64        // HEADS*HID
#define H    8
#define CLS  7
#define EMAX 1600000
#define LRELU 0.2f

// ---------------- scratch (device globals; allocation-free) ----------------
__device__ float g_h1[(size_t)NN * HC];   // layer1 linear output
__device__ float g_as1[NN * H];
__device__ float g_ad1[NN * H];
__device__ float g_x2[(size_t)NN * HC];   // elu(aggregated layer1) = layer2 input
__device__ float g_h2[NN * CLS];
__device__ float g_as2[NN];
__device__ float g_ad2[NN];
__device__ int   g_deg[NN];
__device__ int   g_off[NN + 1];
__device__ int   g_cur[NN];
__device__ int   g_srcs[EMAX];

__device__ __forceinline__ float lrelu(float x) { return x > 0.f ? x : LRELU * x; }

// ---------------- CSR build ----------------
__global__ void k_zero_deg() {
    int i = blockIdx.x * blockDim.x + threadIdx.x;
    if (i < NN) g_deg[i] = 0;
}

__global__ void k_hist(const int* __restrict__ dst, int E) {
    int i = blockIdx.x * blockDim.x + threadIdx.x;
    if (i < E) atomicAdd(&g_deg[dst[i]], 1);
}

// single-block scan (1024 threads), exclusive prefix into g_off / g_cur
__global__ void k_scan() {
    __shared__ int sh[1024];
    __shared__ int s_carry;
    int t = threadIdx.x;
    if (t == 0) s_carry = 0;
    __syncthreads();
    for (int base = 0; base < NN; base += 1024) {
        int i = base + t;
        int v = (i < NN) ? g_deg[i] : 0;
        sh[t] = v;
        __syncthreads();
        #pragma unroll
        for (int off = 1; off < 1024; off <<= 1) {
            int u = (t >= off) ? sh[t - off] : 0;
            __syncthreads();
            sh[t] += u;
            __syncthreads();
        }
        int excl = sh[t] - v;
        int c = s_carry;
        if (i < NN) { g_off[i] = c + excl; g_cur[i] = c + excl; }
        int tot = sh[1023];
        __syncthreads();
        if (t == 0) s_carry = c + tot;
        __syncthreads();
    }
    if (t == 0) g_off[NN] = s_carry;
}

__global__ void k_scatter(const int* __restrict__ src, const int* __restrict__ dst, int E) {
    int i = blockIdx.x * blockDim.x + threadIdx.x;
    if (i < E) {
        int d = dst[i];
        int pos = atomicAdd(&g_cur[d], 1);
        g_srcs[pos] = src[i];
    }
}

// ---------------- layer 1 GEMM: h1 = x @ W1  (N x 512 @ 512 x 64) ----------------
#define BM 64
#define BK 16
__global__ void k_gemm1(const float* __restrict__ x, const float* __restrict__ W) {
    __shared__ float As[BK][BM + 1];
    __shared__ float Bs[BK][HC];
    int tid = threadIdx.x;              // 0..255
    int row0 = blockIdx.x * BM;
    int ty = tid >> 4, tx = tid & 15;
    float acc[4][4] = {};
    for (int k0 = 0; k0 < FIN; k0 += BK) {
        {   // A tile 64x16
            int m = tid >> 2, kq = (tid & 3) * 4;
            int gr = row0 + m;
            float4 v = make_float4(0.f, 0.f, 0.f, 0.f);
            if (gr < NN) v = *(const float4*)&x[(size_t)gr * FIN + k0 + kq];
            As[kq + 0][m] = v.x; As[kq + 1][m] = v.y;
            As[kq + 2][m] = v.z; As[kq + 3][m] = v.w;
        }
        {   // B tile 16x64
            int k = tid >> 4, nq = (tid & 15) * 4;
            *(float4*)&Bs[k][nq] = *(const float4*)&W[(size_t)(k0 + k) * HC + nq];
        }
        __syncthreads();
        #pragma unroll
        for (int kk = 0; kk < BK; kk++) {
            float a[4], b[4];
            #pragma unroll
            for (int i = 0; i < 4; i++) a[i] = As[kk][ty * 4 + i];
            #pragma unroll
            for (int j = 0; j < 4; j++) b[j] = Bs[kk][tx * 4 + j];
            #pragma unroll
            for (int i = 0; i < 4; i++)
                #pragma unroll
                for (int j = 0; j < 4; j++)
                    acc[i][j] = fmaf(a[i], b[j], acc[i][j]);
        }
        __syncthreads();
    }
    #pragma unroll
    for (int i = 0; i < 4; i++) {
        int gr = row0 + ty * 4 + i;
        if (gr < NN) {
            float4 v = make_float4(acc[i][0], acc[i][1], acc[i][2], acc[i][3]);
            *(float4*)&g_h1[(size_t)gr * HC + tx * 4] = v;
        }
    }
}

// ---------------- layer 1 alpha scores ----------------
__global__ void k_alpha1(const float* __restrict__ a_src, const float* __restrict__ a_dst) {
    int idx = blockIdx.x * blockDim.x + threadIdx.x;   // (n, h)
    if (idx >= NN * H) return;
    int n = idx >> 3, h = idx & 7;
    const float* hr = &g_h1[(size_t)n * HC + h * 8];
    float s = 0.f, d = 0.f;
    #pragma unroll
    for (int c = 0; c < 8; c++) {
        float v = hr[c];
        s = fmaf(v, __ldg(&a_src[h * 8 + c]), s);
        d = fmaf(v, __ldg(&a_dst[h * 8 + c]), d);
    }
    g_as1[idx] = s;
    g_ad1[idx] = d;
}

// ---------------- layer 1 aggregation: warp per dst node ----------------
__global__ void k_agg1(const float* __restrict__ b1) {
    int warp = (blockIdx.x * blockDim.x + threadIdx.x) >> 5;
    if (warp >= NN) return;
    int lane = threadIdx.x & 31;
    int n = warp;
    int hh = lane & 7;
    float ad = g_ad1[n * H + hh];
    float e0 = lrelu(g_as1[n * H + hh] + ad);          // self loop
    int beg = g_off[n], end = g_off[n + 1];

    // pass 1: max (4 edges/iter, 8 heads across lanes)
    float mloc = e0;
    for (int i = beg + (lane >> 3); i < end; i += 4) {
        int s = g_srcs[i];
        mloc = fmaxf(mloc, lrelu(g_as1[s * H + hh] + ad));
    }
    mloc = fmaxf(mloc, __shfl_xor_sync(0xffffffffu, mloc, 8));
    mloc = fmaxf(mloc, __shfl_xor_sync(0xffffffffu, mloc, 16));
    float m = mloc;

    // pass 2: exp weights + accumulate (lane owns channels 2*lane, 2*lane+1)
    int hsrc = lane >> 2;                               // head of my channels
    float p0 = expf(e0 - m);
    float denom = p0;                                   // valid in lanes 0..7
    float pm0 = __shfl_sync(0xffffffffu, p0, hsrc);
    float2 hv = *(const float2*)&g_h1[(size_t)n * HC + 2 * lane];
    float ax = pm0 * hv.x, ay = pm0 * hv.y;
    for (int i = beg; i < end; ++i) {
        int s = g_srcs[i];
        float p = 0.f;
        if (lane < 8) {
            float e = lrelu(g_as1[s * H + lane] + ad);
            p = expf(e - m);
            denom += p;
        }
        float pm = __shfl_sync(0xffffffffu, p, hsrc);
        float2 v = *(const float2*)&g_h1[(size_t)s * HC + 2 * lane];
        ax = fmaf(pm, v.x, ax);
        ay = fmaf(pm, v.y, ay);
    }
    float dh = __shfl_sync(0xffffffffu, denom, hsrc);
    float inv = 1.0f / dh;
    float o0 = ax * inv + __ldg(&b1[2 * lane]);
    float o1 = ay * inv + __ldg(&b1[2 * lane + 1]);
    o0 = o0 > 0.f ? o0 : expf(o0) - 1.f;                // ELU
    o1 = o1 > 0.f ? o1 : expf(o1) - 1.f;
    *(float2*)&g_x2[(size_t)n * HC + 2 * lane] = make_float2(o0, o1);
}

// ---------------- layer 2 linear + alpha scores ----------------
__global__ void k_lin2(const float* __restrict__ W2, const float* __restrict__ a_s2,
                       const float* __restrict__ a_d2) {
    __shared__ float sW[HC * CLS];
    __shared__ float sas[CLS], sad[CLS];
    int tid = threadIdx.x;
    for (int j = tid; j < HC * CLS; j += blockDim.x) sW[j] = W2[j];
    if (tid < CLS) { sas[tid] = a_s2[tid]; sad[tid] = a_d2[tid]; }
    __syncthreads();
    int n = blockIdx.x * blockDim.x + tid;
    if (n >= NN) return;
    const float* xr = &g_x2[(size_t)n * HC];
    float h[CLS] = {};
    #pragma unroll 8
    for (int k = 0; k < HC; k++) {
        float xv = xr[k];
        #pragma unroll
        for (int c = 0; c < CLS; c++) h[c] = fmaf(xv, sW[k * CLS + c], h[c]);
    }
    float as = 0.f, adv = 0.f;
    #pragma unroll
    for (int c = 0; c < CLS; c++) {
        g_h2[n * CLS + c] = h[c];
        as  = fmaf(h[c], sas[c], as);
        adv = fmaf(h[c], sad[c], adv);
    }
    g_as2[n] = as;
    g_ad2[n] = adv;
}

// ---------------- layer 2 aggregation + bias + log_softmax ----------------
__global__ void k_agg2(const float* __restrict__ b2, float* __restrict__ out) {
    int n = blockIdx.x * blockDim.x + threadIdx.x;
    if (n >= NN) return;
    float adv = g_ad2[n];
    float e0 = lrelu(g_as2[n] + adv);
    int beg = g_off[n], end = g_off[n + 1];
    float m = e0;
    for (int i = beg; i < end; ++i)
        m = fmaxf(m, lrelu(g_as2[g_srcs[i]] + adv));
    float p0 = expf(e0 - m);
    float den = p0;
    float acc[CLS];
    #pragma unroll
    for (int c = 0; c < CLS; c++) acc[c] = p0 * g_h2[n * CLS + c];
    for (int i = beg; i < end; ++i) {
        int s = g_srcs[i];
        float p = expf(lrelu(g_as2[s] + adv) - m);
        den += p;
        #pragma unroll
        for (int c = 0; c < CLS; c++) acc[c] = fmaf(p, g_h2[s * CLS + c], acc[c]);
    }
    float inv = 1.0f / den;
    float o[CLS];
    #pragma unroll
    for (int c = 0; c < CLS; c++) o[c] = acc[c] * inv + __ldg(&b2[c]);
    float mx = o[0];
    #pragma unroll
    for (int c = 1; c < CLS; c++) mx = fmaxf(mx, o[c]);
    float ssum = 0.f;
    #pragma unroll
    for (int c = 0; c < CLS; c++) ssum += expf(o[c] - mx);
    float lse = logf(ssum);
    #pragma unroll
    for (int c = 0; c < CLS; c++) out[n * CLS + c] = o[c] - mx - lse;
}

// ---------------- launch ----------------
extern "C" void kernel_launch(void* const* d_in, const int* in_sizes, int n_in,
                              void* d_out, int out_size) {
    const float* x     = (const float*)d_in[0];
    const int*   ei    = (const int*)  d_in[1];
    const float* W1    = (const float*)d_in[2];
    const float* as1   = (const float*)d_in[3];
    const float* ad1   = (const float*)d_in[4];
    const float* b1    = (const float*)d_in[5];
    const float* W2    = (const float*)d_in[6];
    const float* as2   = (const float*)d_in[7];
    const float* ad2   = (const float*)d_in[8];
    const float* b2    = (const float*)d_in[9];
    float* out = (float*)d_out;

    int E = in_sizes[1] / 2;
    const int* src = ei;
    const int* dst = ei + E;

    int eb = (E + 255) / 256;

    // CSR build (by dst)
    k_zero_deg<<<(NN + 255) / 256, 256>>>();
    k_hist<<<eb, 256>>>(dst, E);
    k_scan<<<1, 1024>>>();
    k_scatter<<<eb, 256>>>(src, dst, E);

    // layer 1
    k_gemm1<<<(NN + BM - 1) / BM, 256>>>(x, W1);
    k_alpha1<<<(NN * H + 255) / 256, 256>>>(as1, ad1);
    k_agg1<<<(NN * 32 + 255) / 256, 256>>>(b1);   // warp per node

    // layer 2
    k_lin2<<<(NN + 127) / 128, 128>>>(W2, as2, ad2);
    k_agg2<<<(NN + 255) / 256, 256>>>(b2, out);
}

// round 3
// speedup vs baseline: 2.2608x; 2.2608x over previous
#include <cuda_runtime.h>
#include <math.h>

#define NN   100000
#define FIN  512
#define HC   64        // HEADS*HID
#define H    8
#define CLS  7
#define EMAX 1600000
#define LRELU 0.2f
#define NBLK 98        // ceil(NN/1024)

// ---------------- scratch (device globals; allocation-free) ----------------
__device__ float g_h1[(size_t)NN * HC];   // layer1 linear output
__device__ float g_as1[NN * H];
__device__ float g_ad1[NN * H];
__device__ float g_x2[(size_t)NN * HC];   // elu(aggregated layer1) = layer2 input
__device__ float g_h2[NN * CLS];
__device__ float g_as2[NN];
__device__ float g_ad2[NN];
__device__ int   g_deg[NN];
__device__ int   g_off[NN + 1];
__device__ int   g_cur[NN];
__device__ int   g_srcs[EMAX];
__device__ int   g_bsum[128];
__device__ int   g_bcar[128];

__device__ __forceinline__ float lrelu(float x) { return x > 0.f ? x : LRELU * x; }

// packed f32x2 helpers (Blackwell: 2x FFMA throughput vs 3-reg FFMA)
__device__ __forceinline__ unsigned long long pk2(float lo, float hi) {
    unsigned long long r;
    asm("mov.b64 %0, {%1, %2};" : "=l"(r) : "f"(lo), "f"(hi));
    return r;
}
__device__ __forceinline__ void fma2(unsigned long long& d, unsigned long long a, unsigned long long b) {
    asm("fma.rn.f32x2 %0, %1, %2, %3;" : "=l"(d) : "l"(a), "l"(b), "l"(d));
}
__device__ __forceinline__ float2 unpk2(unsigned long long v) {
    float2 f;
    asm("mov.b64 {%0, %1}, %2;" : "=f"(f.x), "=f"(f.y) : "l"(v));
    return f;
}

// ---------------- CSR build ----------------
__global__ void k_zero_deg() {
    int i = blockIdx.x * blockDim.x + threadIdx.x;
    if (i < NN) g_deg[i] = 0;
}

__global__ void k_hist(const int* __restrict__ dst, int E) {
    int i = blockIdx.x * blockDim.x + threadIdx.x;
    if (i < E) atomicAdd(&g_deg[dst[i]], 1);
}

// multi-block scan, phase 1: per-1024-chunk exclusive scan + chunk totals
__global__ void k_scan1() {
    __shared__ int wsum[32];
    int t = threadIdx.x;
    int i = blockIdx.x * 1024 + t;
    int lane = t & 31, wid = t >> 5;
    int v = (i < NN) ? g_deg[i] : 0;
    int s = v;
    #pragma unroll
    for (int off = 1; off < 32; off <<= 1) {
        int u = __shfl_up_sync(0xffffffffu, s, off);
        if (lane >= off) s += u;
    }
    if (lane == 31) wsum[wid] = s;
    __syncthreads();
    if (wid == 0) {
        int ws = wsum[lane];
        #pragma unroll
        for (int off = 1; off < 32; off <<= 1) {
            int u = __shfl_up_sync(0xffffffffu, ws, off);
            if (lane >= off) ws += u;
        }
        wsum[lane] = ws;
    }
    __syncthreads();
    int carry = (wid > 0) ? wsum[wid - 1] : 0;
    int incl = s + carry;
    if (i < NN) g_off[i] = incl - v;           // local exclusive
    if (t == 1023) g_bsum[blockIdx.x] = incl;  // chunk total
}

// phase 2: scan the 98 chunk totals (single block, 128 threads)
__global__ void k_scan2() {
    __shared__ int ws[4];
    int t = threadIdx.x, lane = t & 31, wid = t >> 5;
    int v = (t < NBLK) ? g_bsum[t] : 0;
    int s = v;
    #pragma unroll
    for (int off = 1; off < 32; off <<= 1) {
        int u = __shfl_up_sync(0xffffffffu, s, off);
        if (lane >= off) s += u;
    }
    if (lane == 31) ws[wid] = s;
    __syncthreads();
    int carry = 0;
    for (int w = 0; w < wid; w++) carry += ws[w];
    int incl = s + carry;
    g_bcar[t] = incl - v;
    if (t == 127) g_off[NN] = incl;            // grand total = E
}

// phase 3: add chunk carries
__global__ void k_scan3() {
    int i = blockIdx.x * blockDim.x + threadIdx.x;
    if (i < NN) {
        int o = g_off[i] + g_bcar[i >> 10];
        g_off[i] = o;
        g_cur[i] = o;
    }
}

__global__ void k_scatter(const int* __restrict__ src, const int* __restrict__ dst, int E) {
    int i = blockIdx.x * blockDim.x + threadIdx.x;
    if (i < E) {
        int d = dst[i];
        int pos = atomicAdd(&g_cur[d], 1);
        g_srcs[pos] = src[i];
    }
}

// ---------------- layer 1 GEMM + fused alpha: h1 = x @ W1, as1/ad1 ----------------
// 128x64 tile, 128 threads, 8x8 per thread (thread's 8 cols = one head), f32x2 FMAs
#define GBM 128
#define GBK 16
__global__ __launch_bounds__(128) void k_gemm1(const float* __restrict__ x,
                                               const float* __restrict__ W,
                                               const float* __restrict__ a_src,
                                               const float* __restrict__ a_dst) {
    __shared__ float As[GBK][GBM];   // 8KB
    __shared__ float Bs[GBK][HC];    // 4KB
    int tid = threadIdx.x;
    int row0 = blockIdx.x * GBM;
    int ty = tid >> 3;               // 0..15 -> rows ty*8..ty*8+7
    int tx = tid & 7;                // 0..7  -> head tx, cols tx*8..tx*8+7

    unsigned long long acc[8][4];
    #pragma unroll
    for (int i = 0; i < 8; i++)
        #pragma unroll
        for (int j = 0; j < 4; j++) acc[i][j] = 0ull;

    bool rowok = (row0 + tid) < NN;
    const float* xrow = x + (size_t)(row0 + tid) * FIN;

    for (int k0 = 0; k0 < FIN; k0 += GBK) {
        float4 a0, a1, a2, a3;
        if (rowok) {
            a0 = *(const float4*)(xrow + k0);
            a1 = *(const float4*)(xrow + k0 + 4);
            a2 = *(const float4*)(xrow + k0 + 8);
            a3 = *(const float4*)(xrow + k0 + 12);
        } else {
            a0 = a1 = a2 = a3 = make_float4(0.f, 0.f, 0.f, 0.f);
        }
        int i0 = tid, i1 = tid + 128;
        float4 b0 = *(const float4*)&W[(size_t)(k0 + (i0 >> 4)) * HC + (i0 & 15) * 4];
        float4 b1 = *(const float4*)&W[(size_t)(k0 + (i1 >> 4)) * HC + (i1 & 15) * 4];
        __syncthreads();
        As[0][tid] = a0.x;  As[1][tid] = a0.y;  As[2][tid] = a0.z;  As[3][tid] = a0.w;
        As[4][tid] = a1.x;  As[5][tid] = a1.y;  As[6][tid] = a1.z;  As[7][tid] = a1.w;
        As[8][tid] = a2.x;  As[9][tid] = a2.y;  As[10][tid] = a2.z; As[11][tid] = a2.w;
        As[12][tid] = a3.x; As[13][tid] = a3.y; As[14][tid] = a3.z; As[15][tid] = a3.w;
        *(float4*)&Bs[i0 >> 4][(i0 & 15) * 4] = b0;
        *(float4*)&Bs[i1 >> 4][(i1 & 15) * 4] = b1;
        __syncthreads();
        #pragma unroll
        for (int kk = 0; kk < GBK; kk++) {
            float4 av0 = *(float4*)&As[kk][ty * 8];
            float4 av1 = *(float4*)&As[kk][ty * 8 + 4];
            float4 bv0 = *(float4*)&Bs[kk][tx * 8];
            float4 bv1 = *(float4*)&Bs[kk][tx * 8 + 4];
            unsigned long long bp[4];
            bp[0] = pk2(bv0.x, bv0.y); bp[1] = pk2(bv0.z, bv0.w);
            bp[2] = pk2(bv1.x, bv1.y); bp[3] = pk2(bv1.z, bv1.w);
            float a[8] = {av0.x, av0.y, av0.z, av0.w, av1.x, av1.y, av1.z, av1.w};
            #pragma unroll
            for (int i = 0; i < 8; i++) {
                unsigned long long ap = pk2(a[i], a[i]);
                fma2(acc[i][0], ap, bp[0]);
                fma2(acc[i][1], ap, bp[1]);
                fma2(acc[i][2], ap, bp[2]);
                fma2(acc[i][3], ap, bp[3]);
            }
        }
        __syncthreads();
    }

    // epilogue: store h1 rows + fused per-head alpha scores
    float asw[8], adw[8];
    #pragma unroll
    for (int j = 0; j < 8; j++) {
        asw[j] = __ldg(&a_src[tx * 8 + j]);
        adw[j] = __ldg(&a_dst[tx * 8 + j]);
    }
    #pragma unroll
    for (int i = 0; i < 8; i++) {
        int gr = row0 + ty * 8 + i;
        if (gr < NN) {
            float c[8];
            #pragma unroll
            for (int j = 0; j < 4; j++) {
                float2 f = unpk2(acc[i][j]);
                c[2 * j] = f.x; c[2 * j + 1] = f.y;
            }
            float4 v0 = make_float4(c[0], c[1], c[2], c[3]);
            float4 v1 = make_float4(c[4], c[5], c[6], c[7]);
            *(float4*)&g_h1[(size_t)gr * HC + tx * 8] = v0;
            *(float4*)&g_h1[(size_t)gr * HC + tx * 8 + 4] = v1;
            float s = 0.f, d = 0.f;
            #pragma unroll
            for (int j = 0; j < 8; j++) {
                s = fmaf(c[j], asw[j], s);
                d = fmaf(c[j], adw[j], d);
            }
            g_as1[gr * H + tx] = s;
            g_ad1[gr * H + tx] = d;
        }
    }
}

// ---------------- layer 1 aggregation: warp per dst, shfl-free, no max pass ----------------
__global__ void k_agg1(const float* __restrict__ b1) {
    int warp = (blockIdx.x * blockDim.x + threadIdx.x) >> 5;
    if (warp >= NN) return;
    int lane = threadIdx.x & 31;
    int n = warp;
    int h2 = lane >> 2;                          // head of my 2 channels
    float ad = __ldg(&g_ad1[n * H + h2]);
    float p0 = expf(lrelu(__ldg(&g_as1[n * H + h2]) + ad));  // self loop
    float den = p0;
    float2 hv = *(const float2*)&g_h1[(size_t)n * HC + 2 * lane];
    float ax = p0 * hv.x, ay = p0 * hv.y;
    int beg = g_off[n], end = g_off[n + 1];
    #pragma unroll 2
    for (int i = beg; i < end; ++i) {
        int s = g_srcs[i];
        float p = expf(lrelu(__ldg(&g_as1[s * H + h2]) + ad));
        den += p;
        float2 v = *(const float2*)&g_h1[(size_t)s * HC + 2 * lane];
        ax = fmaf(p, v.x, ax);
        ay = fmaf(p, v.y, ay);
    }
    float inv = 1.0f / den;
    float o0 = fmaf(ax, inv, __ldg(&b1[2 * lane]));
    float o1 = fmaf(ay, inv, __ldg(&b1[2 * lane + 1]));
    o0 = o0 > 0.f ? o0 : expf(o0) - 1.f;         // ELU
    o1 = o1 > 0.f ? o1 : expf(o1) - 1.f;
    *(float2*)&g_x2[(size_t)n * HC + 2 * lane] = make_float2(o0, o1);
}

// ---------------- layer 2 linear + alpha scores ----------------
__global__ void k_lin2(const float* __restrict__ W2, const float* __restrict__ a_s2,
                       const float* __restrict__ a_d2) {
    __shared__ float sW[HC * CLS];
    __shared__ float sas[CLS], sad[CLS];
    int tid = threadIdx.x;
    for (int j = tid; j < HC * CLS; j += blockDim.x) sW[j] = W2[j];
    if (tid < CLS) { sas[tid] = a_s2[tid]; sad[tid] = a_d2[tid]; }
    __syncthreads();
    int n = blockIdx.x * blockDim.x + tid;
    if (n >= NN) return;
    const float* xr = &g_x2[(size_t)n * HC];
    float h[CLS] = {};
    #pragma unroll 8
    for (int k = 0; k < HC; k++) {
        float xv = xr[k];
        #pragma unroll
        for (int c = 0; c < CLS; c++) h[c] = fmaf(xv, sW[k * CLS + c], h[c]);
    }
    float as = 0.f, adv = 0.f;
    #pragma unroll
    for (int c = 0; c < CLS; c++) {
        g_h2[n * CLS + c] = h[c];
        as  = fmaf(h[c], sas[c], as);
        adv = fmaf(h[c], sad[c], adv);
    }
    g_as2[n] = as;
    g_ad2[n] = adv;
}

// ---------------- layer 2 aggregation + bias + log_softmax (no max pass) ----------------
__global__ void k_agg2(const float* __restrict__ b2, float* __restrict__ out) {
    int n = blockIdx.x * blockDim.x + threadIdx.x;
    if (n >= NN) return;
    float adv = g_ad2[n];
    float p0 = expf(lrelu(g_as2[n] + adv));
    float den = p0;
    float acc[CLS];
    #pragma unroll
    for (int c = 0; c < CLS; c++) acc[c] = p0 * g_h2[n * CLS + c];
    int beg = g_off[n], end = g_off[n + 1];
    #pragma unroll 2
    for (int i = beg; i < end; ++i) {
        int s = g_srcs[i];
        float p = expf(lrelu(__ldg(&g_as2[s]) + adv));
        den += p;
        #pragma unroll
        for (int c = 0; c < CLS; c++) acc[c] = fmaf(p, __ldg(&g_h2[s * CLS + c]), acc[c]);
    }
    float inv = 1.0f / den;
    float o[CLS];
    #pragma unroll
    for (int c = 0; c < CLS; c++) o[c] = fmaf(acc[c], inv, __ldg(&b2[c]));
    float mx = o[0];
    #pragma unroll
    for (int c = 1; c < CLS; c++) mx = fmaxf(mx, o[c]);
    float ssum = 0.f;
    #pragma unroll
    for (int c = 0; c < CLS; c++) ssum += expf(o[c] - mx);
    float lse = logf(ssum);
    #pragma unroll
    for (int c = 0; c < CLS; c++) out[n * CLS + c] = o[c] - mx - lse;
}

// ---------------- launch ----------------
extern "C" void kernel_launch(void* const* d_in, const int* in_sizes, int n_in,
                              void* d_out, int out_size) {
    const float* x     = (const float*)d_in[0];
    const int*   ei    = (const int*)  d_in[1];
    const float* W1    = (const float*)d_in[2];
    const float* as1   = (const float*)d_in[3];
    const float* ad1   = (const float*)d_in[4];
    const float* b1    = (const float*)d_in[5];
    const float* W2    = (const float*)d_in[6];
    const float* as2   = (const float*)d_in[7];
    const float* ad2   = (const float*)d_in[8];
    const float* b2    = (const float*)d_in[9];
    float* out = (float*)d_out;

    int E = in_sizes[1] / 2;
    const int* src = ei;
    const int* dst = ei + E;
    int eb = (E + 255) / 256;

    // CSR build (by dst)
    k_zero_deg<<<(NN + 255) / 256, 256>>>();
    k_hist<<<eb, 256>>>(dst, E);
    k_scan1<<<NBLK, 1024>>>();
    k_scan2<<<1, 128>>>();
    k_scan3<<<(NN + 255) / 256, 256>>>();
    k_scatter<<<eb, 256>>>(src, dst, E);

    // layer 1
    k_gemm1<<<(NN + GBM - 1) / GBM, 128>>>(x, W1, as1, ad1);
    k_agg1<<<(NN * 32 + 255) / 256, 256>>>(b1);   // warp per node

    // layer 2
    k_lin2<<<(NN + 127) / 128, 128>>>(W2, as2, ad2);
    k_agg2<<<(NN + 255) / 256, 256>>>(b2, out);
}

// round 6
// speedup vs baseline: 3.1240x; 1.3818x over previous
#include <cuda_runtime.h>
#include <cuda_bf16.h>
#include <math.h>

#define NN   100000
#define FIN  512
#define HC   64        // HEADS*HID
#define H    8
#define CLS  7
#define EMAX 1600000
#define LRELU 0.2f
#define NBLK 98        // ceil(NN/1024)

// ---------------- scratch (device globals; allocation-free) ----------------
__device__ float g_h1[(size_t)NN * HC];   // layer1 linear output
__device__ float g_as1[NN * H];
__device__ float g_ad1[NN * H];
__device__ float g_x2[(size_t)NN * HC];   // elu(aggregated layer1) = layer2 input
__device__ float g_h2[NN * CLS];
__device__ float g_as2[NN];
__device__ float g_ad2[NN];
__device__ int   g_deg[NN];
__device__ int   g_off[NN + 1];
__device__ int   g_cur[NN];
__device__ int   g_srcs[EMAX];
__device__ int   g_bsum[128];
__device__ int   g_bcar[128];

__device__ __forceinline__ float lrelu(float x) { return x > 0.f ? x : LRELU * x; }

// ---------------- CSR build ----------------
__global__ void k_zero_deg() {
    int i = blockIdx.x * blockDim.x + threadIdx.x;
    if (i < NN) g_deg[i] = 0;
}

__global__ void k_hist(const int* __restrict__ dst, int E) {
    int i = blockIdx.x * blockDim.x + threadIdx.x;
    if (i < E) atomicAdd(&g_deg[dst[i]], 1);
}

// multi-block scan, phase 1: per-1024-chunk exclusive scan + chunk totals
__global__ void k_scan1() {
    __shared__ int wsum[32];
    int t = threadIdx.x;
    int i = blockIdx.x * 1024 + t;
    int lane = t & 31, wid = t >> 5;
    int v = (i < NN) ? g_deg[i] : 0;
    int s = v;
    #pragma unroll
    for (int off = 1; off < 32; off <<= 1) {
        int u = __shfl_up_sync(0xffffffffu, s, off);
        if (lane >= off) s += u;
    }
    if (lane == 31) wsum[wid] = s;
    __syncthreads();
    if (wid == 0) {
        int ws = wsum[lane];
        #pragma unroll
        for (int off = 1; off < 32; off <<= 1) {
            int u = __shfl_up_sync(0xffffffffu, ws, off);
            if (lane >= off) ws += u;
        }
        wsum[lane] = ws;
    }
    __syncthreads();
    int carry = (wid > 0) ? wsum[wid - 1] : 0;
    int incl = s + carry;
    if (i < NN) g_off[i] = incl - v;           // local exclusive
    if (t == 1023) g_bsum[blockIdx.x] = incl;  // chunk total
}

// phase 2: scan the 98 chunk totals (single block, 128 threads)
__global__ void k_scan2() {
    __shared__ int ws[4];
    int t = threadIdx.x, lane = t & 31, wid = t >> 5;
    int v = (t < NBLK) ? g_bsum[t] : 0;
    int s = v;
    #pragma unroll
    for (int off = 1; off < 32; off <<= 1) {
        int u = __shfl_up_sync(0xffffffffu, s, off);
        if (lane >= off) s += u;
    }
    if (lane == 31) ws[wid] = s;
    __syncthreads();
    int carry = 0;
    for (int w = 0; w < wid; w++) carry += ws[w];
    int incl = s + carry;
    g_bcar[t] = incl - v;
    if (t == 127) g_off[NN] = incl;            // grand total = E
}

// phase 3: add chunk carries
__global__ void k_scan3() {
    int i = blockIdx.x * blockDim.x + threadIdx.x;
    if (i < NN) {
        int o = g_off[i] + g_bcar[i >> 10];
        g_off[i] = o;
        g_cur[i] = o;
    }
}

__global__ void k_scatter(const int* __restrict__ src, const int* __restrict__ dst, int E) {
    int i = blockIdx.x * blockDim.x + threadIdx.x;
    if (i < E) {
        int d = dst[i];
        int pos = atomicAdd(&g_cur[d], 1);
        g_srcs[pos] = src[i];
    }
}

// ---------------- layer 1 GEMM (tensor cores, split-bf16 x3): h1 = x @ W1 ----------------
// Block tile 128x64, 8 warps (256 thr), warp tile 32x32 (2 m16 x 4 n8 mma frags).
// fp32 emulated as Ah*Bh + Ah*Bl + Al*Bh in bf16 HMMA with fp32 accum (~1e-5 rel err).

#define MMA_OP(d, a, b) asm volatile( \
    "mma.sync.aligned.m16n8k16.row.col.f32.bf16.bf16.f32 " \
    "{%0,%1,%2,%3}, {%4,%5,%6,%7}, {%8,%9}, {%0,%1,%2,%3};" \
    : "+f"(d[0]), "+f"(d[1]), "+f"(d[2]), "+f"(d[3]) \
    : "r"(a[0]), "r"(a[1]), "r"(a[2]), "r"(a[3]), "r"(b[0]), "r"(b[1]))

__global__ __launch_bounds__(256) void k_gemm1_tc(const float* __restrict__ x,
                                                  const float* __restrict__ W) {
    __shared__ __align__(16) __nv_bfloat16 As_hi[128][40];  // 32 k + 8 pad (80B rows)
    __shared__ __align__(16) __nv_bfloat16 As_lo[128][40];
    __shared__ __align__(16) __nv_bfloat16 Bs_hi[32][72];   // 64 n + 8 pad (144B rows)
    __shared__ __align__(16) __nv_bfloat16 Bs_lo[32][72];

    int tid = threadIdx.x;
    int lane = tid & 31, wid = tid >> 5;
    int wm = wid & 3;          // warp m: 0..3 -> rows wm*32
    int wn = wid >> 2;         // warp n: 0..1 -> cols wn*32
    int row0 = blockIdx.x * 128;

    float acc[2][4][4];
    #pragma unroll
    for (int i = 0; i < 2; i++)
        #pragma unroll
        for (int j = 0; j < 4; j++)
            #pragma unroll
            for (int q = 0; q < 4; q++) acc[i][j][q] = 0.f;

    // A load mapping: thread -> (row = tid/2, kq = (tid&1)*16)
    int arow = tid >> 1;
    int akq = (tid & 1) * 16;
    bool aok = (row0 + arow) < NN;
    const float* ap = x + (size_t)(row0 + arow) * FIN + akq;
    // B load mapping: thread -> (k row = tid/8, nq = (tid&7)*8)
    int bkr = tid >> 3;
    int bnq = (tid & 7) * 8;

    // ldmatrix shared addresses (computed per use)
    int lr = lane & 15;        // row-within-16
    int lc8 = (lane >> 4) * 8; // 0 or 8

    for (int k0 = 0; k0 < FIN; k0 += 32) {
        // ---- gmem loads + split conversion (registers) ----
        float va[16];
        if (aok) {
            float4 t0 = *(const float4*)(ap + k0);
            float4 t1 = *(const float4*)(ap + k0 + 4);
            float4 t2 = *(const float4*)(ap + k0 + 8);
            float4 t3 = *(const float4*)(ap + k0 + 12);
            va[0]=t0.x; va[1]=t0.y; va[2]=t0.z; va[3]=t0.w;
            va[4]=t1.x; va[5]=t1.y; va[6]=t1.z; va[7]=t1.w;
            va[8]=t2.x; va[9]=t2.y; va[10]=t2.z; va[11]=t2.w;
            va[12]=t3.x; va[13]=t3.y; va[14]=t3.z; va[15]=t3.w;
        } else {
            #pragma unroll
            for (int e = 0; e < 16; e++) va[e] = 0.f;
        }
        __nv_bfloat16 ah16[16], al16[16];
        #pragma unroll
        for (int e = 0; e < 16; e++) {
            __nv_bfloat16 hv = __float2bfloat16(va[e]);
            ah16[e] = hv;
            al16[e] = __float2bfloat16(va[e] - __bfloat162float(hv));
        }
        float vb[8];
        {
            const float* wp = W + (size_t)(k0 + bkr) * HC + bnq;
            float4 t0 = *(const float4*)(wp);
            float4 t1 = *(const float4*)(wp + 4);
            vb[0]=t0.x; vb[1]=t0.y; vb[2]=t0.z; vb[3]=t0.w;
            vb[4]=t1.x; vb[5]=t1.y; vb[6]=t1.z; vb[7]=t1.w;
        }
        __nv_bfloat16 bh16[8], bl16[8];
        #pragma unroll
        for (int e = 0; e < 8; e++) {
            __nv_bfloat16 hv = __float2bfloat16(vb[e]);
            bh16[e] = hv;
            bl16[e] = __float2bfloat16(vb[e] - __bfloat162float(hv));
        }

        __syncthreads();   // previous iteration's reads done
        *(uint4*)&As_hi[arow][akq]     = *(uint4*)&ah16[0];
        *(uint4*)&As_hi[arow][akq + 8] = *(uint4*)&ah16[8];
        *(uint4*)&As_lo[arow][akq]     = *(uint4*)&al16[0];
        *(uint4*)&As_lo[arow][akq + 8] = *(uint4*)&al16[8];
        *(uint4*)&Bs_hi[bkr][bnq] = *(uint4*)&bh16[0];
        *(uint4*)&Bs_lo[bkr][bnq] = *(uint4*)&bl16[0];
        __syncthreads();

        // ---- compute: two k16 steps ----
        #pragma unroll
        for (int kk = 0; kk < 32; kk += 16) {
            unsigned ah[2][4], al[2][4];
            #pragma unroll
            for (int im = 0; im < 2; im++) {
                unsigned addr_h = (unsigned)__cvta_generic_to_shared(
                    &As_hi[wm * 32 + im * 16 + lr][kk + lc8]);
                asm volatile("ldmatrix.sync.aligned.m8n8.x4.shared.b16 {%0,%1,%2,%3}, [%4];"
                    : "=r"(ah[im][0]), "=r"(ah[im][1]), "=r"(ah[im][2]), "=r"(ah[im][3])
                    : "r"(addr_h));
                unsigned addr_l = (unsigned)__cvta_generic_to_shared(
                    &As_lo[wm * 32 + im * 16 + lr][kk + lc8]);
                asm volatile("ldmatrix.sync.aligned.m8n8.x4.shared.b16 {%0,%1,%2,%3}, [%4];"
                    : "=r"(al[im][0]), "=r"(al[im][1]), "=r"(al[im][2]), "=r"(al[im][3])
                    : "r"(addr_l));
            }
            unsigned bh[4][2], bl[4][2];
            #pragma unroll
            for (int nh = 0; nh < 2; nh++) {
                unsigned r0, r1, r2, r3;
                unsigned addr_h = (unsigned)__cvta_generic_to_shared(
                    &Bs_hi[kk + lr][wn * 32 + nh * 16 + lc8]);
                asm volatile("ldmatrix.sync.aligned.m8n8.x4.trans.shared.b16 {%0,%1,%2,%3}, [%4];"
                    : "=r"(r0), "=r"(r1), "=r"(r2), "=r"(r3) : "r"(addr_h));
                bh[nh * 2 + 0][0] = r0; bh[nh * 2 + 0][1] = r1;
                bh[nh * 2 + 1][0] = r2; bh[nh * 2 + 1][1] = r3;
                unsigned addr_l = (unsigned)__cvta_generic_to_shared(
                    &Bs_lo[kk + lr][wn * 32 + nh * 16 + lc8]);
                asm volatile("ldmatrix.sync.aligned.m8n8.x4.trans.shared.b16 {%0,%1,%2,%3}, [%4];"
                    : "=r"(r0), "=r"(r1), "=r"(r2), "=r"(r3) : "r"(addr_l));
                bl[nh * 2 + 0][0] = r0; bl[nh * 2 + 0][1] = r1;
                bl[nh * 2 + 1][0] = r2; bl[nh * 2 + 1][1] = r3;
            }
            #pragma unroll
            for (int im = 0; im < 2; im++) {
                #pragma unroll
                for (int in = 0; in < 4; in++) {
                    MMA_OP(acc[im][in], ah[im], bh[in]);
                    MMA_OP(acc[im][in], ah[im], bl[in]);
                    MMA_OP(acc[im][in], al[im], bh[in]);
                }
            }
        }
    }

    // ---- epilogue: write h1 ----
    int r = lane >> 2;
    int cq = (lane & 3) * 2;
    #pragma unroll
    for (int im = 0; im < 2; im++) {
        #pragma unroll
        for (int in = 0; in < 4; in++) {
            int m = row0 + wm * 32 + im * 16 + r;
            int col = wn * 32 + in * 8 + cq;
            if (m < NN)
                *(float2*)&g_h1[(size_t)m * HC + col] =
                    make_float2(acc[im][in][0], acc[im][in][1]);
            if (m + 8 < NN)
                *(float2*)&g_h1[(size_t)(m + 8) * HC + col] =
                    make_float2(acc[im][in][2], acc[im][in][3]);
        }
    }
}

// ---------------- layer 1 alpha scores ----------------
__global__ void k_alpha1(const float* __restrict__ a_src, const float* __restrict__ a_dst) {
    int idx = blockIdx.x * blockDim.x + threadIdx.x;   // (n, h)
    if (idx >= NN * H) return;
    int n = idx >> 3, h = idx & 7;
    const float* hr = &g_h1[(size_t)n * HC + h * 8];
    float s = 0.f, d = 0.f;
    #pragma unroll
    for (int c = 0; c < 8; c++) {
        float v = hr[c];
        s = fmaf(v, __ldg(&a_src[h * 8 + c]), s);
        d = fmaf(v, __ldg(&a_dst[h * 8 + c]), d);
    }
    g_as1[idx] = s;
    g_ad1[idx] = d;
}

// ---------------- layer 1 aggregation: warp per dst, shfl-free, no max pass ----------------
__global__ void k_agg1(const float* __restrict__ b1) {
    int warp = (blockIdx.x * blockDim.x + threadIdx.x) >> 5;
    if (warp >= NN) return;
    int lane = threadIdx.x & 31;
    int n = warp;
    int h2 = lane >> 2;                          // head of my 2 channels
    float ad = __ldg(&g_ad1[n * H + h2]);
    float p0 = expf(lrelu(__ldg(&g_as1[n * H + h2]) + ad));  // self loop
    float den = p0;
    float2 hv = *(const float2*)&g_h1[(size_t)n * HC + 2 * lane];
    float ax = p0 * hv.x, ay = p0 * hv.y;
    int beg = g_off[n], end = g_off[n + 1];
    #pragma unroll 2
    for (int i = beg; i < end; ++i) {
        int s = g_srcs[i];
        float p = expf(lrelu(__ldg(&g_as1[s * H + h2]) + ad));
        den += p;
        float2 v = *(const float2*)&g_h1[(size_t)s * HC + 2 * lane];
        ax = fmaf(p, v.x, ax);
        ay = fmaf(p, v.y, ay);
    }
    float inv = 1.0f / den;
    float o0 = fmaf(ax, inv, __ldg(&b1[2 * lane]));
    float o1 = fmaf(ay, inv, __ldg(&b1[2 * lane + 1]));
    o0 = o0 > 0.f ? o0 : expf(o0) - 1.f;         // ELU
    o1 = o1 > 0.f ? o1 : expf(o1) - 1.f;
    *(float2*)&g_x2[(size_t)n * HC + 2 * lane] = make_float2(o0, o1);
}

// ---------------- layer 2 linear + alpha scores ----------------
__global__ void k_lin2(const float* __restrict__ W2, const float* __restrict__ a_s2,
                       const float* __restrict__ a_d2) {
    __shared__ float sW[HC * CLS];
    __shared__ float sas[CLS], sad[CLS];
    int tid = threadIdx.x;
    for (int j = tid; j < HC * CLS; j += blockDim.x) sW[j] = W2[j];
    if (tid < CLS) { sas[tid] = a_s2[tid]; sad[tid] = a_d2[tid]; }
    __syncthreads();
    int n = blockIdx.x * blockDim.x + tid;
    if (n >= NN) return;
    const float* xr = &g_x2[(size_t)n * HC];
    float h[CLS] = {};
    #pragma unroll 8
    for (int k = 0; k < HC; k++) {
        float xv = xr[k];
        #pragma unroll
        for (int c = 0; c < CLS; c++) h[c] = fmaf(xv, sW[k * CLS + c], h[c]);
    }
    float as = 0.f, adv = 0.f;
    #pragma unroll
    for (int c = 0; c < CLS; c++) {
        g_h2[n * CLS + c] = h[c];
        as  = fmaf(h[c], sas[c], as);
        adv = fmaf(h[c], sad[c], adv);
    }
    g_as2[n] = as;
    g_ad2[n] = adv;
}

// ---------------- layer 2 aggregation + bias + log_softmax (no max pass) ----------------
__global__ void k_agg2(const float* __restrict__ b2, float* __restrict__ out) {
    int n = blockIdx.x * blockDim.x + threadIdx.x;
    if (n >= NN) return;
    float adv = g_ad2[n];
    float p0 = expf(lrelu(g_as2[n] + adv));
    float den = p0;
    float acc[CLS];
    #pragma unroll
    for (int c = 0; c < CLS; c++) acc[c] = p0 * g_h2[n * CLS + c];
    int beg = g_off[n], end = g_off[n + 1];
    #pragma unroll 2
    for (int i = beg; i < end; ++i) {
        int s = g_srcs[i];
        float p = expf(lrelu(__ldg(&g_as2[s]) + adv));
        den += p;
        #pragma unroll
        for (int c = 0; c < CLS; c++) acc[c] = fmaf(p, __ldg(&g_h2[s * CLS + c]), acc[c]);
    }
    float inv = 1.0f / den;
    float o[CLS];
    #pragma unroll
    for (int c = 0; c < CLS; c++) o[c] = fmaf(acc[c], inv, __ldg(&b2[c]));
    float mx = o[0];
    #pragma unroll
    for (int c = 1; c < CLS; c++) mx = fmaxf(mx, o[c]);
    float ssum = 0.f;
    #pragma unroll
    for (int c = 0; c < CLS; c++) ssum += expf(o[c] - mx);
    float lse = logf(ssum);
    #pragma unroll
    for (int c = 0; c < CLS; c++) out[n * CLS + c] = o[c] - mx - lse;
}

// ---------------- launch ----------------
extern "C" void kernel_launch(void* const* d_in, const int* in_sizes, int n_in,
                              void* d_out, int out_size) {
    const float* x     = (const float*)d_in[0];
    const int*   ei    = (const int*)  d_in[1];
    const float* W1    = (const float*)d_in[2];
    const float* as1   = (const float*)d_in[3];
    const float* ad1   = (const float*)d_in[4];
    const float* b1    = (const float*)d_in[5];
    const float* W2    = (const float*)d_in[6];
    const float* as2   = (const float*)d_in[7];
    const float* ad2   = (const float*)d_in[8];
    const float* b2    = (const float*)d_in[9];
    float* out = (float*)d_out;

    int E = in_sizes[1] / 2;
    const int* src = ei;
    const int* dst = ei + E;
    int eb = (E + 255) / 256;

    // launch order puts k_gemm1_tc 4th (ncu profiles the 4th launch)
    k_zero_deg<<<(NN + 255) / 256, 256>>>();                 // 1
    k_hist<<<eb, 256>>>(dst, E);                             // 2
    k_scan1<<<NBLK, 1024>>>();                               // 3
    k_gemm1_tc<<<(NN + 127) / 128, 256>>>(x, W1);            // 4  <- profiled
    k_alpha1<<<(NN * H + 255) / 256, 256>>>(as1, ad1);       // 5
    k_scan2<<<1, 128>>>();                                   // 6
    k_scan3<<<(NN + 255) / 256, 256>>>();                    // 7
    k_scatter<<<eb, 256>>>(src, dst, E);                     // 8
    k_agg1<<<(NN * 32 + 255) / 256, 256>>>(b1);              // 9
    k_lin2<<<(NN + 127) / 128, 128>>>(W2, as2, ad2);         // 10
    k_agg2<<<(NN + 255) / 256, 256>>>(b2, out);              // 11
}